// round 16
// baseline (speedup 1.0000x reference)
#include <cuda_runtime.h>
#include <cuda_bf16.h>
#include <cuda_fp16.h>
#include <cstdint>

#define EPSV 1e-5f
#define Bq 4
#define Nq 4096
#define Kq 32
#define INq 256
#define SCq 128
#define OUTq 512
#define SNK (Nq*Kq)        /* 131072 samples per b for gcm */

// ---------------- scratch (device globals; no allocation allowed) ----------
__device__ float g_sub_raw[(size_t)Bq*Nq*SCq];       // (b,n,c)   8.4 MB
__device__ uint32_t g_ygcm2[(size_t)Bq*(SNK/2)*SCq]; // (b,pair,c) half2  134 MB
__device__ float g_pooledT[(size_t)Bq*SCq*Nq];       // (b,c,n)   8.4 MB
__device__ float g_yup[(size_t)Bq*OUTq*Nq];          // (b,o,n)   33.5 MB
__device__ float g_yres[(size_t)Bq*OUTq*Nq];         // (b,o,n)   33.5 MB
__device__ unsigned short g_wgcm_h[SCq*INq];         // gcm weights, single fp16
__device__ __nv_bfloat16 g_wsub_hi[SCq*INq];         // bf16 splits for lin kernels
__device__ __nv_bfloat16 g_wsub_lo[SCq*INq];
__device__ __nv_bfloat16 g_wup_hi[OUTq*SCq];
__device__ __nv_bfloat16 g_wup_lo[OUTq*SCq];
__device__ __nv_bfloat16 g_wres_hi[OUTq*INq];
__device__ __nv_bfloat16 g_wres_lo[OUTq*INq];
// stat slots: sub [0,128) gcm [128,256) up [256,768) res [768,1280)
__device__ float g_ssum[1280];
__device__ float g_ssq[1280];
__device__ float g_scl[1280];
__device__ float g_sft[1280];

// ---------------- helpers ----------------------------------------------------
__device__ __forceinline__ uint32_t smem_u32(const void* p){
  uint32_t a;
  asm("{ .reg .u64 t; cvta.to.shared.u64 t, %1; cvt.u32.u64 %0, t; }" : "=r"(a) : "l"(p));
  return a;
}
// swizzle: permute low 3 bits of 16B-chunk index by f (3-bit)
__device__ __forceinline__ int chunk_sw(int c, int f){ return (c & ~7) | ((c & 7) ^ f); }
__device__ __forceinline__ int swf(int r){ return (r & 7) ^ ((r >> 3) & 7); }

#define LDM4(r, ad) \
  asm volatile("ldmatrix.sync.aligned.m8n8.x4.shared.b16 {%0,%1,%2,%3}, [%4];" \
    : "=r"((r)[0]),"=r"((r)[1]),"=r"((r)[2]),"=r"((r)[3]) : "r"(ad))
#define LDM4T(r, ad) \
  asm volatile("ldmatrix.sync.aligned.m8n8.x4.trans.shared.b16 {%0,%1,%2,%3}, [%4];" \
    : "=r"((r)[0]),"=r"((r)[1]),"=r"((r)[2]),"=r"((r)[3]) : "r"(ad))
#define MMA16816(d, a, bb) \
  asm volatile("mma.sync.aligned.m16n8k16.row.col.f32.bf16.bf16.f32 " \
    "{%0,%1,%2,%3}, {%4,%5,%6,%7}, {%8,%9}, {%0,%1,%2,%3};" \
    : "+f"((d)[0]), "+f"((d)[1]), "+f"((d)[2]), "+f"((d)[3]) \
    : "r"((a)[0]), "r"((a)[1]), "r"((a)[2]), "r"((a)[3]), "r"((bb)[0]), "r"((bb)[1]))
#define MMAF16(d, a, bb) \
  asm volatile("mma.sync.aligned.m16n8k16.row.col.f32.f16.f16.f32 " \
    "{%0,%1,%2,%3}, {%4,%5,%6,%7}, {%8,%9}, {%0,%1,%2,%3};" \
    : "+f"((d)[0]), "+f"((d)[1]), "+f"((d)[2]), "+f"((d)[3]) \
    : "r"((a)[0]), "r"((a)[1]), "r"((a)[2]), "r"((a)[3]), "r"((bb)[0]), "r"((bb)[1]))

// pack (v0,v1) -> bf16x2 hi + bf16x2 lo (residual) — lin kernels
__device__ __forceinline__ uint32_t pack2(float v0, float v1, uint32_t& lo){
  uint32_t hi;
  asm("cvt.rn.bf16x2.f32 %0, %1, %2;" : "=r"(hi) : "f"(v1), "f"(v0));
  float h0 = __uint_as_float(hi << 16);
  float h1 = __uint_as_float(hi & 0xffff0000u);
  float l0 = v0 - h0, l1 = v1 - h1;
  asm("cvt.rn.bf16x2.f32 %0, %1, %2;" : "=r"(lo) : "f"(l1), "f"(l0));
  return hi;
}
// pack (v0,v1) -> fp16x2 — gcm operands / ygcm store
__device__ __forceinline__ uint32_t packh(float v0, float v1){
  uint32_t h;
  asm("cvt.rn.f16x2.f32 %0, %1, %2;" : "=r"(h) : "f"(v1), "f"(v0));
  return h;
}

// ---------------- prep: zero stats + split all weights ----------------------
__global__ void prep_all_kernel(const float* __restrict__ wsub,
                                const float* __restrict__ wgcm,
                                const float* __restrict__ wup,
                                const float* __restrict__ wres){
  int i = blockIdx.x*256 + threadIdx.x;
  if (i < 1280){ g_ssum[i]=0.f; g_ssq[i]=0.f; }
  int j = i;
  if (j < 32768){
    float f = wsub[j];
    __nv_bfloat16 h = __float2bfloat16_rn(f);
    g_wsub_hi[j] = h;
    g_wsub_lo[j] = __float2bfloat16_rn(f - __bfloat162float(h));
  } else if (j < 65536){
    j -= 32768;
    g_wgcm_h[j] = __half_as_ushort(__float2half_rn(wgcm[j]));
  } else if (j < 131072){
    j -= 65536;
    float f = wup[j];
    __nv_bfloat16 h = __float2bfloat16_rn(f);
    g_wup_hi[j] = h;
    g_wup_lo[j] = __float2bfloat16_rn(f - __bfloat162float(h));
  } else {
    j -= 131072;
    float f = wres[j];
    __nv_bfloat16 h = __float2bfloat16_rn(f);
    g_wres_hi[j] = h;
    g_wres_lo[j] = __float2bfloat16_rn(f - __bfloat162float(h));
  }
}

__global__ void finalize_kernel(const float* __restrict__ g, const float* __restrict__ be,
                                int off, int n, float invc){
  int i = blockIdx.x*blockDim.x + threadIdx.x;
  if (i >= n) return;
  float m = g_ssum[off+i]*invc;
  float v = g_ssq[off+i]*invc - m*m;
  float sc = g[i]*rsqrtf(v + EPSV);
  g_scl[off+i] = sc;
  g_sft[off+i] = be[i] - m*sc;
}

// merged finalize for up [256,768) + res [768,1280)
__global__ void finalize2_kernel(const float* __restrict__ g1, const float* __restrict__ be1,
                                 const float* __restrict__ g2, const float* __restrict__ be2){
  int i = blockIdx.x*128 + threadIdx.x;     // 0..1023
  const float invc = 1.f/16384.f;
  if (i < 512){
    float m = g_ssum[256+i]*invc;
    float v = g_ssq[256+i]*invc - m*m;
    float sc = g1[i]*rsqrtf(v + EPSV);
    g_scl[256+i] = sc;  g_sft[256+i] = be1[i] - m*sc;
  } else {
    int k = i - 512;
    float m = g_ssum[768+k]*invc;
    float v = g_ssq[768+k]*invc - m*m;
    float sc = g2[k]*rsqrtf(v + EPSV);
    g_scl[768+k] = sc;  g_sft[768+k] = be2[k] - m*sc;
  }
}

// ---------------- gcm conv: single-fp16 mma.sync + fused gather -------------
// A = W in fp16 (64 KB resident). B = X in fp16. Double-buffered 64-k-row
// chunks; 2 CTAs/SM. Output ygcm stored as half2 (sample pair per channel).
#define GA_H 0
#define GB_BASE 65536           /* buf p at +p*16384 */
#define G_SCL 98304
#define G_SFT 98816
#define G_SMEM 99328
#define G_TILES 4

__device__ __forceinline__ void stage_exp(char* smem, uint32_t buf,
    const float* __restrict__ expf_b, int chbase, int s0, int tid)
{
  int kr = tid >> 2, nh = (tid & 3) * 32;
  const float* src = expf_b + (size_t)(chbase + kr)*(size_t)SNK + s0 + nh;
  int fkr = swf(kr);
  float f[32];
  #pragma unroll
  for (int q = 0; q < 8; q++) *(float4*)&f[q*4] = *(const float4*)&src[q*4];
  #pragma unroll
  for (int e = 0; e < 4; e++){
    uint32_t hi[4];
    #pragma unroll
    for (int p = 0; p < 4; p++)
      hi[p] = packh(f[e*8+p*2], f[e*8+p*2+1]);
    uint32_t off = (uint32_t)(kr*256 + chunk_sw(nh/8 + e, fkr)*16);
    *(uint4*)(smem + buf + off) = make_uint4(hi[0],hi[1],hi[2],hi[3]);
  }
}

__device__ __forceinline__ void stage_gat(char* smem, uint32_t buf,
    const float* __restrict__ subraw_b, const int* __restrict__ gidx_b,
    int chbase, int s0, int tid)
{
  int jp = tid >> 2, cq = tid & 3;
  int j0 = jp*2, ch0 = cq*16;
  int i0 = gidx_b[s0 + j0];
  int i1 = gidx_b[s0 + j0 + 1];
  const float* r0p = subraw_b + (size_t)i0*128 + chbase + ch0;
  const float* r1p = subraw_b + (size_t)i1*128 + chbase + ch0;
  float f0[16], f1[16];
  #pragma unroll
  for (int q = 0; q < 4; q++){
    *(float4*)&f0[q*4] = *(const float4*)&r0p[q*4];
    *(float4*)&f1[q*4] = *(const float4*)&r1p[q*4];
  }
  const int cb = j0 >> 3, jo = (j0 & 7)*2;
  #pragma unroll
  for (int ci = 0; ci < 16; ci++){
    int chL = ch0 + ci;              // local B row
    int chG = chbase + chL;          // global sub channel
    float s = *(const float*)(smem + G_SCL + chG*4);
    float t = *(const float*)(smem + G_SFT + chG*4);
    float v0 = fmaxf(fmaf(s, f0[ci], t), 0.f);
    float v1 = fmaxf(fmaf(s, f1[ci], t), 0.f);
    uint32_t off = (uint32_t)(chL*256 + chunk_sw(cb, swf(chL))*16 + jo);
    *(uint32_t*)(smem + buf + off) = packh(v0, v1);
  }
}

__device__ __forceinline__ void stage_chunk(char* smem, int chunk, int buf,
    const float* __restrict__ expf_b, const float* __restrict__ subraw_b,
    const int* __restrict__ gidx_b, int s0, int tid)
{
  uint32_t bufOff = GB_BASE + (uint32_t)buf*16384;
  if (chunk < 2) stage_exp(smem, bufOff, expf_b, chunk*64, s0, tid);
  else           stage_gat(smem, bufOff, subraw_b, gidx_b, (chunk-2)*64, s0, tid);
}

__global__ __launch_bounds__(256,2) void gcm_mma_kernel(
    const float* __restrict__ expf, const float* __restrict__ subraw,
    const int* __restrict__ gidx, const float* __restrict__ bias,
    uint32_t* __restrict__ ygcm2)
{
  extern __shared__ char smem[];
  const uint32_t sb = smem_u32(smem);
  const int tid = threadIdx.x;
  const int lane = tid & 31, wid = tid >> 5;
  const int wm = wid >> 1, wn = wid & 1;          // warp grid 4m x 2n
  const int b = blockIdx.x >> 8;                  // 256 CTAs per b
  const int tile0 = (blockIdx.x & 255) * G_TILES;
  const float* expf_b   = expf   + (size_t)b*128*(size_t)SNK;
  const float* subraw_b = subraw + (size_t)b*Nq*128;
  const int*   gidx_b   = gidx   + (size_t)b*SNK;

  if (tid < 128){
    *(float*)(smem + G_SCL + tid*4) = g_scl[tid];
    *(float*)(smem + G_SFT + tid*4) = g_sft[tid];
  }
  // ---- load A (fp16 weights) into swizzled SMEM, once per CTA -------------
  {
    int m = tid >> 1, kh = (tid & 1) * 128;
    int fm = swf(m);
    #pragma unroll
    for (int e = 0; e < 16; e++){
      int k = kh + e*8;
      uint32_t off = (uint32_t)(m*512 + chunk_sw(k >> 3, fm)*16);
      *(uint4*)(smem + GA_H + off) = *(const uint4*)&g_wgcm_h[m*256 + k];
    }
  }
  __syncthreads();

  const int a_lk = lane >> 4;
  int aOff[2]; int aF[2];
  #pragma unroll
  for (int mB = 0; mB < 2; mB++){
    int m = wm*32 + mB*16 + ((lane >> 3) & 1)*8 + (lane & 7);
    aOff[mB] = m*512; aF[mB] = swf(m);
  }
  const int b_k = lane & 15, b_cadd = lane >> 4;
  const int g = lane >> 2, l2 = lane & 3;

  // hoisted bias
  float bA[2], bB[2];
  #pragma unroll
  for (int mB = 0; mB < 2; mB++){
    int m1 = wm*32 + mB*16 + g;
    bA[mB] = bias[m1]; bB[mB] = bias[m1+8];
  }

  float psum[2][2], psq[2][2];
  #pragma unroll
  for (int i=0;i<2;i++){ psum[i][0]=psum[i][1]=0.f; psq[i][0]=psq[i][1]=0.f; }

  // preload tile0 chunk0
  stage_chunk(smem, 0, 0, expf_b, subraw_b, gidx_b, tile0*128, tid);
  __syncthreads();

  for (int it = 0; it < G_TILES; it++){
    const int s0 = (tile0 + it) * 128;
    float acc[2][8][4];
    #pragma unroll
    for (int i=0;i<2;i++)
      #pragma unroll
      for (int j=0;j<8;j++)
        #pragma unroll
        for (int q=0;q<4;q++) acc[i][j][q] = 0.f;

    #pragma unroll
    for (int c = 0; c < 4; c++){
      // stage next chunk into the other buffer (overlaps MMA via warp interleave)
      if (c < 3)
        stage_chunk(smem, c+1, (c+1)&1, expf_b, subraw_b, gidx_b, s0, tid);
      else if (it + 1 < G_TILES)
        stage_chunk(smem, 0, 0, expf_b, subraw_b, gidx_b, s0 + 128, tid);
      // MMA on current chunk (4 ksteps of 16)
      const uint32_t bufB = sb + GB_BASE + (uint32_t)(c&1)*16384;
      #pragma unroll
      for (int ks = 0; ks < 4; ks++){
        int kg = c*64 + ks*16;
        uint32_t ah[2][4];
        #pragma unroll
        for (int mB = 0; mB < 2; mB++){
          int cc = (kg >> 3) + a_lk;
          uint32_t off = (uint32_t)(aOff[mB] + chunk_sw(cc, aF[mB])*16);
          LDM4(ah[mB], sb + GA_H + off);
        }
        uint32_t bh[8][2];
        #pragma unroll
        for (int nB2 = 0; nB2 < 4; nB2++){
          int kl = ks*16 + b_k;
          int cn = wn*8 + nB2*2 + b_cadd;
          uint32_t off = (uint32_t)(kl*256 + chunk_sw(cn, swf(kl))*16);
          uint32_t r[4];
          LDM4T(r, bufB + off);
          bh[nB2*2][0]=r[0]; bh[nB2*2][1]=r[1];
          bh[nB2*2+1][0]=r[2]; bh[nB2*2+1][1]=r[3];
        }
        #pragma unroll
        for (int mB = 0; mB < 2; mB++)
          #pragma unroll
          for (int nB = 0; nB < 8; nB++)
            MMAF16(acc[mB][nB], ah[mB], bh[nB]);
      }
      __syncthreads();
    }
    // ---- epilogue: bias, store ygcm as half2 pairs, stat partials ---------
    #pragma unroll
    for (int mB = 0; mB < 2; mB++){
      float b1 = bA[mB], b2 = bB[mB];
      int m1 = wm*32 + mB*16 + g;
      #pragma unroll
      for (int nB = 0; nB < 8; nB++){
        int n = wn*64 + nB*8 + l2*2;                 // even sample index
        size_t rp = (size_t)(((size_t)b*SNK + s0 + n) >> 1) * 128;
        float v0 = acc[mB][nB][0] + b1;
        float v1 = acc[mB][nB][1] + b1;
        float v2 = acc[mB][nB][2] + b2;
        float v3 = acc[mB][nB][3] + b2;
        ygcm2[rp + m1]     = packh(v0, v1);          // channel m1, samples n/n+1
        ygcm2[rp + m1 + 8] = packh(v2, v3);          // channel m1+8
        psum[mB][0] += v0 + v1;  psq[mB][0] += v0*v0 + v1*v1;
        psum[mB][1] += v2 + v3;  psq[mB][1] += v2*v2 + v3*v3;
      }
    }
  }
  #pragma unroll
  for (int mB = 0; mB < 2; mB++)
    #pragma unroll
    for (int h = 0; h < 2; h++){
      float s = psum[mB][h], q = psq[mB][h];
      s += __shfl_down_sync(0xffffffffu, s, 1, 4);
      s += __shfl_down_sync(0xffffffffu, s, 2, 4);
      q += __shfl_down_sync(0xffffffffu, q, 1, 4);
      q += __shfl_down_sync(0xffffffffu, q, 2, 4);
      if (l2 == 0){
        int m = wm*32 + mB*16 + g + h*8;
        atomicAdd(&g_ssum[128 + m], s);
        atomicAdd(&g_ssq [128 + m], q);
      }
    }
}

// ---------------- generic linear conv via mma.sync (split bf16 x3) ----------
template<int KDIM, bool SMAJOR>
__global__ __launch_bounds__(256,1) void lin_mma_kernel(
    const __nv_bfloat16* __restrict__ whi, const __nv_bfloat16* __restrict__ wlo,
    const float* __restrict__ X, const float* __restrict__ bias,
    float* __restrict__ Y, int statOff, int SPB, int Mtot)
{
  constexpr int AB = 128*KDIM*2;          // bytes per A buffer
  constexpr int NKC = KDIM/128;
  extern __shared__ char smem[];
  const uint32_t sb = smem_u32(smem);
  const uint32_t A_HI = 0, A_LO = AB, B_HI = 2*AB, B_LO = 2*AB + 32768;
  const int tid = threadIdx.x;
  const int lane = tid & 31, wid = tid >> 5;
  const int wm = wid >> 2, wn = wid & 3;
  const int b = blockIdx.z;
  const int s0 = blockIdx.x * 128;
  const int m0 = blockIdx.y * 128;

  // load A (128 x KDIM hi/lo) into swizzled SMEM
  {
    int m = tid >> 1, kh = (tid & 1) * (KDIM/2);
    int fm = swf(m);
    #pragma unroll
    for (int e = 0; e < KDIM/16; e++){
      int k = kh + e*8;
      uint32_t off = (uint32_t)(m*(KDIM*2) + chunk_sw(k >> 3, fm)*16);
      *(uint4*)(smem + A_HI + off) = *(const uint4*)&whi[(size_t)(m0+m)*KDIM + k];
      *(uint4*)(smem + A_LO + off) = *(const uint4*)&wlo[(size_t)(m0+m)*KDIM + k];
    }
  }
  __syncthreads();

  const int a_lk = lane >> 4;
  int aOff[4]; int aF[4];
  #pragma unroll
  for (int mB = 0; mB < 4; mB++){
    int m = wm*64 + mB*16 + ((lane >> 3) & 1)*8 + (lane & 7);
    aOff[mB] = m*(KDIM*2); aF[mB] = swf(m);
  }
  const int b_k = lane & 15, b_cadd = lane >> 4;
  const int g = lane >> 2, l2 = lane & 3;

  float acc[4][4][4];
  #pragma unroll
  for (int i=0;i<4;i++)
    #pragma unroll
    for (int j=0;j<4;j++)
      #pragma unroll
      for (int q=0;q<4;q++) acc[i][j][q] = 0.f;

  #pragma unroll
  for (int kc = 0; kc < NKC; kc++){
    {
      int kr = tid >> 1, nh = (tid & 1) * 64;
      int fkr = swf(kr);
      const float* src = X + ((size_t)b*KDIM + kc*128 + kr)*(size_t)SPB + s0 + nh;
      #pragma unroll
      for (int hh = 0; hh < 2; hh++){
        float f[32];
        #pragma unroll
        for (int q = 0; q < 8; q++)
          *(float4*)&f[q*4] = *(const float4*)&src[hh*32 + q*4];
        #pragma unroll
        for (int e = 0; e < 4; e++){
          uint32_t hi[4], lo[4];
          #pragma unroll
          for (int p = 0; p < 4; p++)
            hi[p] = pack2(f[e*8+p*2], f[e*8+p*2+1], lo[p]);
          int c = (nh + hh*32)/8 + e;
          uint32_t off = (uint32_t)(kr*256 + chunk_sw(c, fkr)*16);
          *(uint4*)(smem + B_HI + off) = make_uint4(hi[0],hi[1],hi[2],hi[3]);
          *(uint4*)(smem + B_LO + off) = make_uint4(lo[0],lo[1],lo[2],lo[3]);
        }
      }
    }
    __syncthreads();
    #pragma unroll
    for (int ks = 0; ks < 8; ks++){
      int kg = kc*128 + ks*16;
      uint32_t ah[4][4], al[4][4];
      #pragma unroll
      for (int mB = 0; mB < 4; mB++){
        int c = (kg >> 3) + a_lk;
        uint32_t off = (uint32_t)(aOff[mB] + chunk_sw(c, aF[mB])*16);
        LDM4(ah[mB], sb + A_HI + off);
        LDM4(al[mB], sb + A_LO + off);
      }
      uint32_t bh[4][2], bl[4][2];
      #pragma unroll
      for (int nB2 = 0; nB2 < 2; nB2++){
        int kl = ks*16 + b_k;
        int cn = wn*4 + nB2*2 + b_cadd;
        uint32_t off = (uint32_t)(kl*256 + chunk_sw(cn, swf(kl))*16);
        uint32_t r[4];
        LDM4T(r, sb + B_HI + off);
        bh[nB2*2][0]=r[0]; bh[nB2*2][1]=r[1];
        bh[nB2*2+1][0]=r[2]; bh[nB2*2+1][1]=r[3];
        LDM4T(r, sb + B_LO + off);
        bl[nB2*2][0]=r[0]; bl[nB2*2][1]=r[1];
        bl[nB2*2+1][0]=r[2]; bl[nB2*2+1][1]=r[3];
      }
      #pragma unroll
      for (int mB = 0; mB < 4; mB++)
        #pragma unroll
        for (int nB = 0; nB < 4; nB++){
          MMA16816(acc[mB][nB], ah[mB], bh[nB]);
          MMA16816(acc[mB][nB], ah[mB], bl[nB]);
          MMA16816(acc[mB][nB], al[mB], bh[nB]);
        }
    }
    __syncthreads();
  }

  float psum[4][2], psq[4][2];
  #pragma unroll
  for (int i=0;i<4;i++){ psum[i][0]=psum[i][1]=0.f; psq[i][0]=psq[i][1]=0.f; }

  #pragma unroll
  for (int mB = 0; mB < 4; mB++){
    int m1 = wm*64 + mB*16 + g;
    float b1 = bias[m0 + m1], b2 = bias[m0 + m1 + 8];
    #pragma unroll
    for (int nB = 0; nB < 4; nB++){
      int n = wn*32 + nB*8 + l2*2;
      float v0 = acc[mB][nB][0] + b1;
      float v1 = acc[mB][nB][1] + b1;
      float v2 = acc[mB][nB][2] + b2;
      float v3 = acc[mB][nB][3] + b2;
      if (SMAJOR){
        size_t r0 = ((size_t)b*SPB + s0 + n)*(size_t)Mtot + m0;
        Y[r0 + m1]                = v0;
        Y[r0 + Mtot + m1]         = v1;
        Y[r0 + m1 + 8]            = v2;
        Y[r0 + Mtot + m1 + 8]     = v3;
      } else {
        size_t r0 = ((size_t)b*Mtot + m0 + m1)*(size_t)SPB + s0 + n;
        float2 p01; p01.x = v0; p01.y = v1;
        *(float2*)&Y[r0] = p01;
        float2 p23; p23.x = v2; p23.y = v3;
        *(float2*)&Y[r0 + 8*(size_t)SPB] = p23;
      }
      psum[mB][0] += v0 + v1;  psq[mB][0] += v0*v0 + v1*v1;
      psum[mB][1] += v2 + v3;  psq[mB][1] += v2*v2 + v3*v3;
    }
  }
  #pragma unroll
  for (int mB = 0; mB < 4; mB++)
    #pragma unroll
    for (int h = 0; h < 2; h++){
      float s = psum[mB][h], q = psq[mB][h];
      s += __shfl_down_sync(0xffffffffu, s, 1, 4);
      s += __shfl_down_sync(0xffffffffu, s, 2, 4);
      q += __shfl_down_sync(0xffffffffu, q, 1, 4);
      q += __shfl_down_sync(0xffffffffu, q, 2, 4);
      if (l2 == 0){
        int m = m0 + wm*64 + mB*16 + g + h*8;
        atomicAdd(&g_ssum[statOff + m], s);
        atomicAdd(&g_ssq [statOff + m], q);
      }
    }
}

// ---------------- BN(gcm)+relu, attention softmax over c, max-pool over k ---
// reads half2 pairs (samples 2p,2p+1)
__global__ __launch_bounds__(128) void attnpool_kernel(
    const uint32_t* __restrict__ ygcm2, const float* __restrict__ w_att,
    const float* __restrict__ b_att, float* __restrict__ pooledT)
{
  __shared__ float watt[32];
  __shared__ float redm[4], reds[4];
  const int c = threadIdx.x;
  const int bn = blockIdx.x;                 // b*4096 + n
  if (c < 32) watt[c] = w_att[c];
  const float sc = g_scl[128+c], sh = g_sft[128+c];
  __syncthreads();
  const uint32_t* base = ygcm2 + (size_t)bn*16*128 + c;
  float logit = 0.f, mx = 0.f;
  #pragma unroll
  for (int p = 0; p < 16; p++){
    uint32_t u = base[(size_t)p*128];
    float2 f = __half22float2(*(__half2*)&u);
    float va = fmaxf(fmaf(sc, f.x, sh), 0.f);
    float vb = fmaxf(fmaf(sc, f.y, sh), 0.f);
    logit = fmaf(va, watt[2*p], fmaf(vb, watt[2*p+1], logit));
    mx = fmaxf(mx, fmaxf(va, vb));
  }
  logit += b_att[0];
  const int lane = c & 31, w = c >> 5;
  float m = logit;
  #pragma unroll
  for (int o=16;o>0;o>>=1) m = fmaxf(m, __shfl_xor_sync(0xffffffffu, m, o));
  if (lane==0) redm[w] = m;
  __syncthreads();
  m = fmaxf(fmaxf(redm[0],redm[1]), fmaxf(redm[2],redm[3]));
  float e = expf(logit - m);
  float s = e;
  #pragma unroll
  for (int o=16;o>0;o>>=1) s += __shfl_xor_sync(0xffffffffu, s, o);
  if (lane==0) reds[w] = s;
  __syncthreads();
  float tot = reds[0]+reds[1]+reds[2]+reds[3];
  float pooled = fmaf(mx, e/tot, mx);
  const int b = bn >> 12, n = bn & 4095;
  pooledT[((size_t)b*SCq + c)*(size_t)Nq + n] = pooled;
}

// ---------------- final: relu(bn(up)) + relu(bn(res)) -----------------------
__global__ __launch_bounds__(256) void combine_kernel(float* __restrict__ out){
  size_t i4 = (size_t)blockIdx.x*256 + threadIdx.x;
  size_t i = i4*4;
  int o = (int)((i >> 12) & 511);
  float su = g_scl[256+o], tu = g_sft[256+o];
  float sr = g_scl[768+o], th = g_sft[768+o];
  float4 u = *(const float4*)&g_yup[i];
  float4 r = *(const float4*)&g_yres[i];
  float4 y;
  y.x = fmaxf(fmaf(su,u.x,tu),0.f) + fmaxf(fmaf(sr,r.x,th),0.f);
  y.y = fmaxf(fmaf(su,u.y,tu),0.f) + fmaxf(fmaf(sr,r.y,th),0.f);
  y.z = fmaxf(fmaf(su,u.z,tu),0.f) + fmaxf(fmaf(sr,r.z,th),0.f);
  y.w = fmaxf(fmaf(su,u.w,tu),0.f) + fmaxf(fmaf(sr,r.w,th),0.f);
  *(float4*)&out[i] = y;
}

// ---------------- launch ----------------------------------------------------
extern "C" void kernel_launch(void* const* d_in, const int* in_sizes, int n_in,
                              void* d_out, int out_size){
  (void)in_sizes; (void)n_in; (void)out_size;
  const float* expanded = (const float*)d_in[0];
  const float* feature  = (const float*)d_in[1];
  const int*   gidx     = (const int*)d_in[2];
  const float* w_sub = (const float*)d_in[3];
  const float* b_sub = (const float*)d_in[4];
  const float* gg_sub= (const float*)d_in[5];
  const float* be_sub= (const float*)d_in[6];
  const float* w_gcm = (const float*)d_in[7];
  const float* b_gcm = (const float*)d_in[8];
  const float* gg_gcm= (const float*)d_in[9];
  const float* be_gcm= (const float*)d_in[10];
  const float* w_att = (const float*)d_in[11];
  const float* b_att = (const float*)d_in[12];
  const float* w_up  = (const float*)d_in[13];
  const float* b_up  = (const float*)d_in[14];
  const float* gg_up = (const float*)d_in[15];
  const float* be_up = (const float*)d_in[16];
  const float* w_res = (const float*)d_in[17];
  const float* b_res = (const float*)d_in[18];
  const float* gg_res= (const float*)d_in[19];
  const float* be_res= (const float*)d_in[20];
  float* out = (float*)d_out;

  float *p_subraw, *p_pool, *p_yup, *p_yres;
  uint32_t* p_ygcm2;
  cudaGetSymbolAddress((void**)&p_subraw, g_sub_raw);
  cudaGetSymbolAddress((void**)&p_ygcm2,  g_ygcm2);
  cudaGetSymbolAddress((void**)&p_pool,   g_pooledT);
  cudaGetSymbolAddress((void**)&p_yup,    g_yup);
  cudaGetSymbolAddress((void**)&p_yres,   g_yres);
  __nv_bfloat16 *p_wsub_hi, *p_wsub_lo, *p_wup_hi, *p_wup_lo, *p_wres_hi, *p_wres_lo;
  cudaGetSymbolAddress((void**)&p_wsub_hi, g_wsub_hi);
  cudaGetSymbolAddress((void**)&p_wsub_lo, g_wsub_lo);
  cudaGetSymbolAddress((void**)&p_wup_hi,  g_wup_hi);
  cudaGetSymbolAddress((void**)&p_wup_lo,  g_wup_lo);
  cudaGetSymbolAddress((void**)&p_wres_hi, g_wres_hi);
  cudaGetSymbolAddress((void**)&p_wres_lo, g_wres_lo);

  cudaFuncSetAttribute(gcm_mma_kernel,
                       cudaFuncAttributeMaxDynamicSharedMemorySize, G_SMEM);
  cudaFuncSetAttribute(lin_mma_kernel<256,true>,
                       cudaFuncAttributeMaxDynamicSharedMemorySize, 196608);
  cudaFuncSetAttribute(lin_mma_kernel<256,false>,
                       cudaFuncAttributeMaxDynamicSharedMemorySize, 196608);
  cudaFuncSetAttribute(lin_mma_kernel<128,false>,
                       cudaFuncAttributeMaxDynamicSharedMemorySize, 131072);

  // 1: zero stats + split all weights
  prep_all_kernel<<<1024, 256>>>(w_sub, w_gcm, w_up, w_res);
  // 2: sub conv -> sub_raw (b,n,c) + stats[0..128)
  lin_mma_kernel<256,true><<<dim3(32,1,4), 256, 196608>>>(
      p_wsub_hi, p_wsub_lo, feature, b_sub, p_subraw, 0, Nq, 128);
  // 3
  finalize_kernel<<<1,128>>>(gg_sub, be_sub, 0, 128, 1.f/16384.f);
  // 4: gcm conv (single fp16, fused gather + BN(sub)) — ncu window target
  gcm_mma_kernel<<<1024, 256, G_SMEM>>>(
      expanded, p_subraw, gidx, b_gcm, p_ygcm2);
  // 5
  finalize_kernel<<<1,128>>>(gg_gcm, be_gcm, 128, 128, 1.f/524288.f);
  // 6: attention + max-pool -> pooledT (b,c,n)
  attnpool_kernel<<<Bq*Nq,128>>>(p_ygcm2, w_att, b_att, p_pool);
  // 7: up conv (K=128) -> yup (b,o,n) + stats[256..768)
  lin_mma_kernel<128,false><<<dim3(32,4,4), 256, 131072>>>(
      p_wup_hi, p_wup_lo, p_pool, b_up, p_yup, 256, Nq, 512);
  // 8: res conv (K=256) -> yres (b,o,n) + stats[768..1280)
  lin_mma_kernel<256,false><<<dim3(32,4,4), 256, 196608>>>(
      p_wres_hi, p_wres_lo, feature, b_res, p_yres, 768, Nq, 512);
  // 9
  finalize2_kernel<<<8,128>>>(gg_up, be_up, gg_res, be_res);
  // 10: out = relu(bn(up)) + relu(bn(res))
  combine_kernel<<<8192,256>>>(out);
}

// round 17
// speedup vs baseline: 1.0511x; 1.0511x over previous
#include <cuda_runtime.h>
#include <cuda_bf16.h>
#include <cuda_fp16.h>
#include <cstdint>

#define EPSV 1e-5f
#define Bq 4
#define Nq 4096
#define Kq 32
#define INq 256
#define SCq 128
#define OUTq 512
#define SNK (Nq*Kq)        /* 131072 samples per b for gcm */

// ---------------- scratch (device globals; no allocation allowed) ----------
__device__ float g_sub_raw[(size_t)Bq*Nq*SCq];       // (b,n,c)   8.4 MB
__device__ uint32_t g_ygcm2[(size_t)Bq*(SNK/2)*SCq]; // (b,pair,c) half2  134 MB
__device__ float g_pooledT[(size_t)Bq*SCq*Nq];       // (b,c,n)   8.4 MB
__device__ float g_yup[(size_t)Bq*OUTq*Nq];          // (b,o,n)   33.5 MB
__device__ float g_yres[(size_t)Bq*OUTq*Nq];         // (b,o,n)   33.5 MB
__device__ unsigned short g_wgcm_h[SCq*INq];         // gcm weights, single fp16
__device__ __nv_bfloat16 g_wsub_hi[SCq*INq];         // bf16 splits for lin kernels
__device__ __nv_bfloat16 g_wsub_lo[SCq*INq];
__device__ __nv_bfloat16 g_wup_hi[OUTq*SCq];
__device__ __nv_bfloat16 g_wup_lo[OUTq*SCq];
__device__ __nv_bfloat16 g_wres_hi[OUTq*INq];
__device__ __nv_bfloat16 g_wres_lo[OUTq*INq];
// stat slots: sub [0,128) gcm [128,256) up [256,768) res [768,1280)
__device__ float g_ssum[1280];
__device__ float g_ssq[1280];
__device__ float g_scl[1280];
__device__ float g_sft[1280];

// ---------------- helpers ----------------------------------------------------
__device__ __forceinline__ uint32_t smem_u32(const void* p){
  uint32_t a;
  asm("{ .reg .u64 t; cvta.to.shared.u64 t, %1; cvt.u32.u64 %0, t; }" : "=r"(a) : "l"(p));
  return a;
}
// swizzle: permute low 3 bits of 16B-chunk index by f (3-bit)
__device__ __forceinline__ int chunk_sw(int c, int f){ return (c & ~7) | ((c & 7) ^ f); }
__device__ __forceinline__ int swf(int r){ return (r & 7) ^ ((r >> 3) & 7); }

#define LDM4(r, ad) \
  asm volatile("ldmatrix.sync.aligned.m8n8.x4.shared.b16 {%0,%1,%2,%3}, [%4];" \
    : "=r"((r)[0]),"=r"((r)[1]),"=r"((r)[2]),"=r"((r)[3]) : "r"(ad))
#define LDM4T(r, ad) \
  asm volatile("ldmatrix.sync.aligned.m8n8.x4.trans.shared.b16 {%0,%1,%2,%3}, [%4];" \
    : "=r"((r)[0]),"=r"((r)[1]),"=r"((r)[2]),"=r"((r)[3]) : "r"(ad))
#define MMA16816(d, a, bb) \
  asm volatile("mma.sync.aligned.m16n8k16.row.col.f32.bf16.bf16.f32 " \
    "{%0,%1,%2,%3}, {%4,%5,%6,%7}, {%8,%9}, {%0,%1,%2,%3};" \
    : "+f"((d)[0]), "+f"((d)[1]), "+f"((d)[2]), "+f"((d)[3]) \
    : "r"((a)[0]), "r"((a)[1]), "r"((a)[2]), "r"((a)[3]), "r"((bb)[0]), "r"((bb)[1]))
#define MMAF16(d, a, bb) \
  asm volatile("mma.sync.aligned.m16n8k16.row.col.f32.f16.f16.f32 " \
    "{%0,%1,%2,%3}, {%4,%5,%6,%7}, {%8,%9}, {%0,%1,%2,%3};" \
    : "+f"((d)[0]), "+f"((d)[1]), "+f"((d)[2]), "+f"((d)[3]) \
    : "r"((a)[0]), "r"((a)[1]), "r"((a)[2]), "r"((a)[3]), "r"((bb)[0]), "r"((bb)[1]))

// pack (v0,v1) -> bf16x2 hi + bf16x2 lo (residual) — lin kernels
__device__ __forceinline__ uint32_t pack2(float v0, float v1, uint32_t& lo){
  uint32_t hi;
  asm("cvt.rn.bf16x2.f32 %0, %1, %2;" : "=r"(hi) : "f"(v1), "f"(v0));
  float h0 = __uint_as_float(hi << 16);
  float h1 = __uint_as_float(hi & 0xffff0000u);
  float l0 = v0 - h0, l1 = v1 - h1;
  asm("cvt.rn.bf16x2.f32 %0, %1, %2;" : "=r"(lo) : "f"(l1), "f"(l0));
  return hi;
}
// pack (v0,v1) -> fp16x2 — gcm operands / ygcm store
__device__ __forceinline__ uint32_t packh(float v0, float v1){
  uint32_t h;
  asm("cvt.rn.f16x2.f32 %0, %1, %2;" : "=r"(h) : "f"(v1), "f"(v0));
  return h;
}

// ---------------- prep: zero stats + split all weights ----------------------
__global__ void prep_all_kernel(const float* __restrict__ wsub,
                                const float* __restrict__ wgcm,
                                const float* __restrict__ wup,
                                const float* __restrict__ wres){
  int i = blockIdx.x*256 + threadIdx.x;
  if (i < 1280){ g_ssum[i]=0.f; g_ssq[i]=0.f; }
  int j = i;
  if (j < 32768){
    float f = wsub[j];
    __nv_bfloat16 h = __float2bfloat16_rn(f);
    g_wsub_hi[j] = h;
    g_wsub_lo[j] = __float2bfloat16_rn(f - __bfloat162float(h));
  } else if (j < 65536){
    j -= 32768;
    g_wgcm_h[j] = __half_as_ushort(__float2half_rn(wgcm[j]));
  } else if (j < 131072){
    j -= 65536;
    float f = wup[j];
    __nv_bfloat16 h = __float2bfloat16_rn(f);
    g_wup_hi[j] = h;
    g_wup_lo[j] = __float2bfloat16_rn(f - __bfloat162float(h));
  } else {
    j -= 131072;
    float f = wres[j];
    __nv_bfloat16 h = __float2bfloat16_rn(f);
    g_wres_hi[j] = h;
    g_wres_lo[j] = __float2bfloat16_rn(f - __bfloat162float(h));
  }
}

__global__ void finalize_kernel(const float* __restrict__ g, const float* __restrict__ be,
                                int off, int n, float invc){
  int i = blockIdx.x*blockDim.x + threadIdx.x;
  if (i >= n) return;
  float m = g_ssum[off+i]*invc;
  float v = g_ssq[off+i]*invc - m*m;
  float sc = g[i]*rsqrtf(v + EPSV);
  g_scl[off+i] = sc;
  g_sft[off+i] = be[i] - m*sc;
}

// merged finalize for up [256,768) + res [768,1280)
__global__ void finalize2_kernel(const float* __restrict__ g1, const float* __restrict__ be1,
                                 const float* __restrict__ g2, const float* __restrict__ be2){
  int i = blockIdx.x*128 + threadIdx.x;     // 0..1023
  const float invc = 1.f/16384.f;
  if (i < 512){
    float m = g_ssum[256+i]*invc;
    float v = g_ssq[256+i]*invc - m*m;
    float sc = g1[i]*rsqrtf(v + EPSV);
    g_scl[256+i] = sc;  g_sft[256+i] = be1[i] - m*sc;
  } else {
    int k = i - 512;
    float m = g_ssum[768+k]*invc;
    float v = g_ssq[768+k]*invc - m*m;
    float sc = g2[k]*rsqrtf(v + EPSV);
    g_scl[768+k] = sc;  g_sft[768+k] = be2[k] - m*sc;
  }
}

// ---------------- gcm conv: single-fp16 mma.sync + fused gather -------------
// A = W in fp16 (64 KB resident). B = X in fp16. Double-buffered 64-k-row
// chunks; 2 CTAs/SM. Flattened tile space: 4096 global tiles over 592 CTAs
// (= exactly 2 waves at 2 CTAs/SM on 148 SMs) to kill wave quantization.
#define GA_H 0
#define GB_BASE 65536           /* buf p at +p*16384 */
#define G_SCL 98304
#define G_SFT 98816
#define G_SMEM 99328
#define G_CTAS 592
#define G_NTILES 4096           /* 4 b * 1024 tiles; tile t: b=t>>10, s0=(t&1023)*128 */

__device__ __forceinline__ void stage_exp(char* smem, uint32_t buf,
    const float* __restrict__ expf, int b, int chbase, int s0, int tid)
{
  int kr = tid >> 2, nh = (tid & 3) * 32;
  const float* src = expf + ((size_t)b*128 + chbase + kr)*(size_t)SNK + s0 + nh;
  int fkr = swf(kr);
  float f[32];
  #pragma unroll
  for (int q = 0; q < 8; q++) *(float4*)&f[q*4] = *(const float4*)&src[q*4];
  #pragma unroll
  for (int e = 0; e < 4; e++){
    uint32_t hi[4];
    #pragma unroll
    for (int p = 0; p < 4; p++)
      hi[p] = packh(f[e*8+p*2], f[e*8+p*2+1]);
    uint32_t off = (uint32_t)(kr*256 + chunk_sw(nh/8 + e, fkr)*16);
    *(uint4*)(smem + buf + off) = make_uint4(hi[0],hi[1],hi[2],hi[3]);
  }
}

__device__ __forceinline__ void stage_gat(char* smem, uint32_t buf,
    const float* __restrict__ subraw, const int* __restrict__ gidx,
    int b, int chbase, int s0, int tid)
{
  int jp = tid >> 2, cq = tid & 3;
  int j0 = jp*2, ch0 = cq*16;
  const int* gixp = gidx + (size_t)b*SNK + s0 + j0;
  int i0 = gixp[0];
  int i1 = gixp[1];
  const float* r0p = subraw + ((size_t)b*Nq + i0)*128 + chbase + ch0;
  const float* r1p = subraw + ((size_t)b*Nq + i1)*128 + chbase + ch0;
  float f0[16], f1[16];
  #pragma unroll
  for (int q = 0; q < 4; q++){
    *(float4*)&f0[q*4] = *(const float4*)&r0p[q*4];
    *(float4*)&f1[q*4] = *(const float4*)&r1p[q*4];
  }
  const int cb = j0 >> 3, jo = (j0 & 7)*2;
  #pragma unroll
  for (int ci = 0; ci < 16; ci++){
    int chL = ch0 + ci;              // local B row
    int chG = chbase + chL;          // global sub channel
    float s = *(const float*)(smem + G_SCL + chG*4);
    float t = *(const float*)(smem + G_SFT + chG*4);
    float v0 = fmaxf(fmaf(s, f0[ci], t), 0.f);
    float v1 = fmaxf(fmaf(s, f1[ci], t), 0.f);
    uint32_t off = (uint32_t)(chL*256 + chunk_sw(cb, swf(chL))*16 + jo);
    *(uint32_t*)(smem + buf + off) = packh(v0, v1);
  }
}

// chunk 0/1 = expanded_f channels [0,64)/[64,128)
// chunk 2/3 = relu(bn(sub_raw[gidx])) channels [0,64)/[64,128)
__device__ __forceinline__ void stage_chunk(char* smem, int chunk, int buf,
    const float* __restrict__ expf, const float* __restrict__ subraw,
    const int* __restrict__ gidx, int t, int tid)
{
  uint32_t bufOff = GB_BASE + (uint32_t)buf*16384;
  int b = t >> 10, s0 = (t & 1023) * 128;
  if (chunk < 2) stage_exp(smem, bufOff, expf, b, chunk*64, s0, tid);
  else           stage_gat(smem, bufOff, subraw, gidx, b, (chunk-2)*64, s0, tid);
}

__global__ __launch_bounds__(256,2) void gcm_mma_kernel(
    const float* __restrict__ expf, const float* __restrict__ subraw,
    const int* __restrict__ gidx, const float* __restrict__ bias,
    uint32_t* __restrict__ ygcm2)
{
  extern __shared__ char smem[];
  const uint32_t sb = smem_u32(smem);
  const int tid = threadIdx.x;
  const int lane = tid & 31, wid = tid >> 5;
  const int wm = wid >> 1, wn = wid & 1;          // warp grid 4m x 2n
  const int bid = blockIdx.x;
  const int t0 = (int)(((long long)bid * G_NTILES) / G_CTAS);
  const int t1 = (int)(((long long)(bid+1) * G_NTILES) / G_CTAS);

  if (tid < 128){
    *(float*)(smem + G_SCL + tid*4) = g_scl[tid];
    *(float*)(smem + G_SFT + tid*4) = g_sft[tid];
  }
  // ---- load A (fp16 weights) into swizzled SMEM, once per CTA -------------
  {
    int m = tid >> 1, kh = (tid & 1) * 128;
    int fm = swf(m);
    #pragma unroll
    for (int e = 0; e < 16; e++){
      int k = kh + e*8;
      uint32_t off = (uint32_t)(m*512 + chunk_sw(k >> 3, fm)*16);
      *(uint4*)(smem + GA_H + off) = *(const uint4*)&g_wgcm_h[m*256 + k];
    }
  }
  __syncthreads();

  const int a_lk = lane >> 4;
  int aOff[2]; int aF[2];
  #pragma unroll
  for (int mB = 0; mB < 2; mB++){
    int m = wm*32 + mB*16 + ((lane >> 3) & 1)*8 + (lane & 7);
    aOff[mB] = m*512; aF[mB] = swf(m);
  }
  const int b_k = lane & 15, b_cadd = lane >> 4;
  const int g = lane >> 2, l2 = lane & 3;

  // hoisted bias
  float bA[2], bB[2];
  #pragma unroll
  for (int mB = 0; mB < 2; mB++){
    int m1 = wm*32 + mB*16 + g;
    bA[mB] = bias[m1]; bB[mB] = bias[m1+8];
  }

  float psum[2][2], psq[2][2];
  #pragma unroll
  for (int i=0;i<2;i++){ psum[i][0]=psum[i][1]=0.f; psq[i][0]=psq[i][1]=0.f; }

  // preload first tile's chunk0
  stage_chunk(smem, 0, 0, expf, subraw, gidx, t0, tid);
  __syncthreads();

  for (int t = t0; t < t1; t++){
    const int b = t >> 10;
    const int s0 = (t & 1023) * 128;
    float acc[2][8][4];
    #pragma unroll
    for (int i=0;i<2;i++)
      #pragma unroll
      for (int j=0;j<8;j++)
        #pragma unroll
        for (int q=0;q<4;q++) acc[i][j][q] = 0.f;

    #pragma unroll
    for (int c = 0; c < 4; c++){
      // stage next chunk into the other buffer (overlaps MMA via warp interleave)
      if (c < 3)
        stage_chunk(smem, c+1, (c+1)&1, expf, subraw, gidx, t, tid);
      else if (t + 1 < t1)
        stage_chunk(smem, 0, 0, expf, subraw, gidx, t+1, tid);
      // MMA on current chunk (4 ksteps of 16)
      const uint32_t bufB = sb + GB_BASE + (uint32_t)(c&1)*16384;
      #pragma unroll
      for (int ks = 0; ks < 4; ks++){
        int kg = c*64 + ks*16;
        uint32_t ah[2][4];
        #pragma unroll
        for (int mB = 0; mB < 2; mB++){
          int cc = (kg >> 3) + a_lk;
          uint32_t off = (uint32_t)(aOff[mB] + chunk_sw(cc, aF[mB])*16);
          LDM4(ah[mB], sb + GA_H + off);
        }
        uint32_t bh[8][2];
        #pragma unroll
        for (int nB2 = 0; nB2 < 4; nB2++){
          int kl = ks*16 + b_k;
          int cn = wn*8 + nB2*2 + b_cadd;
          uint32_t off = (uint32_t)(kl*256 + chunk_sw(cn, swf(kl))*16);
          uint32_t r[4];
          LDM4T(r, bufB + off);
          bh[nB2*2][0]=r[0]; bh[nB2*2][1]=r[1];
          bh[nB2*2+1][0]=r[2]; bh[nB2*2+1][1]=r[3];
        }
        #pragma unroll
        for (int mB = 0; mB < 2; mB++)
          #pragma unroll
          for (int nB = 0; nB < 8; nB++)
            MMAF16(acc[mB][nB], ah[mB], bh[nB]);
      }
      __syncthreads();
    }
    // ---- epilogue: bias, store ygcm as half2 pairs, stat partials ---------
    #pragma unroll
    for (int mB = 0; mB < 2; mB++){
      float b1 = bA[mB], b2 = bB[mB];
      int m1 = wm*32 + mB*16 + g;
      #pragma unroll
      for (int nB = 0; nB < 8; nB++){
        int n = wn*64 + nB*8 + l2*2;                 // even sample index
        size_t rp = (size_t)(((size_t)b*SNK + s0 + n) >> 1) * 128;
        float v0 = acc[mB][nB][0] + b1;
        float v1 = acc[mB][nB][1] + b1;
        float v2 = acc[mB][nB][2] + b2;
        float v3 = acc[mB][nB][3] + b2;
        ygcm2[rp + m1]     = packh(v0, v1);          // channel m1, samples n/n+1
        ygcm2[rp + m1 + 8] = packh(v2, v3);          // channel m1+8
        psum[mB][0] += v0 + v1;  psq[mB][0] += v0*v0 + v1*v1;
        psum[mB][1] += v2 + v3;  psq[mB][1] += v2*v2 + v3*v3;
      }
    }
  }
  #pragma unroll
  for (int mB = 0; mB < 2; mB++)
    #pragma unroll
    for (int h = 0; h < 2; h++){
      float s = psum[mB][h], q = psq[mB][h];
      s += __shfl_down_sync(0xffffffffu, s, 1, 4);
      s += __shfl_down_sync(0xffffffffu, s, 2, 4);
      q += __shfl_down_sync(0xffffffffu, q, 1, 4);
      q += __shfl_down_sync(0xffffffffu, q, 2, 4);
      if (l2 == 0){
        int m = wm*32 + mB*16 + g + h*8;
        atomicAdd(&g_ssum[128 + m], s);
        atomicAdd(&g_ssq [128 + m], q);
      }
    }
}

// ---------------- generic linear conv via mma.sync (split bf16 x3) ----------
template<int KDIM, bool SMAJOR>
__global__ __launch_bounds__(256,1) void lin_mma_kernel(
    const __nv_bfloat16* __restrict__ whi, const __nv_bfloat16* __restrict__ wlo,
    const float* __restrict__ X, const float* __restrict__ bias,
    float* __restrict__ Y, int statOff, int SPB, int Mtot)
{
  constexpr int AB = 128*KDIM*2;          // bytes per A buffer
  constexpr int NKC = KDIM/128;
  extern __shared__ char smem[];
  const uint32_t sb = smem_u32(smem);
  const uint32_t A_HI = 0, A_LO = AB, B_HI = 2*AB, B_LO = 2*AB + 32768;
  const int tid = threadIdx.x;
  const int lane = tid & 31, wid = tid >> 5;
  const int wm = wid >> 2, wn = wid & 3;
  const int b = blockIdx.z;
  const int s0 = blockIdx.x * 128;
  const int m0 = blockIdx.y * 128;

  // load A (128 x KDIM hi/lo) into swizzled SMEM
  {
    int m = tid >> 1, kh = (tid & 1) * (KDIM/2);
    int fm = swf(m);
    #pragma unroll
    for (int e = 0; e < KDIM/16; e++){
      int k = kh + e*8;
      uint32_t off = (uint32_t)(m*(KDIM*2) + chunk_sw(k >> 3, fm)*16);
      *(uint4*)(smem + A_HI + off) = *(const uint4*)&whi[(size_t)(m0+m)*KDIM + k];
      *(uint4*)(smem + A_LO + off) = *(const uint4*)&wlo[(size_t)(m0+m)*KDIM + k];
    }
  }
  __syncthreads();

  const int a_lk = lane >> 4;
  int aOff[4]; int aF[4];
  #pragma unroll
  for (int mB = 0; mB < 4; mB++){
    int m = wm*64 + mB*16 + ((lane >> 3) & 1)*8 + (lane & 7);
    aOff[mB] = m*(KDIM*2); aF[mB] = swf(m);
  }
  const int b_k = lane & 15, b_cadd = lane >> 4;
  const int g = lane >> 2, l2 = lane & 3;

  float acc[4][4][4];
  #pragma unroll
  for (int i=0;i<4;i++)
    #pragma unroll
    for (int j=0;j<4;j++)
      #pragma unroll
      for (int q=0;q<4;q++) acc[i][j][q] = 0.f;

  #pragma unroll
  for (int kc = 0; kc < NKC; kc++){
    {
      int kr = tid >> 1, nh = (tid & 1) * 64;
      int fkr = swf(kr);
      const float* src = X + ((size_t)b*KDIM + kc*128 + kr)*(size_t)SPB + s0 + nh;
      #pragma unroll
      for (int hh = 0; hh < 2; hh++){
        float f[32];
        #pragma unroll
        for (int q = 0; q < 8; q++)
          *(float4*)&f[q*4] = *(const float4*)&src[hh*32 + q*4];
        #pragma unroll
        for (int e = 0; e < 4; e++){
          uint32_t hi[4], lo[4];
          #pragma unroll
          for (int p = 0; p < 4; p++)
            hi[p] = pack2(f[e*8+p*2], f[e*8+p*2+1], lo[p]);
          int c = (nh + hh*32)/8 + e;
          uint32_t off = (uint32_t)(kr*256 + chunk_sw(c, fkr)*16);
          *(uint4*)(smem + B_HI + off) = make_uint4(hi[0],hi[1],hi[2],hi[3]);
          *(uint4*)(smem + B_LO + off) = make_uint4(lo[0],lo[1],lo[2],lo[3]);
        }
      }
    }
    __syncthreads();
    #pragma unroll
    for (int ks = 0; ks < 8; ks++){
      int kg = kc*128 + ks*16;
      uint32_t ah[4][4], al[4][4];
      #pragma unroll
      for (int mB = 0; mB < 4; mB++){
        int c = (kg >> 3) + a_lk;
        uint32_t off = (uint32_t)(aOff[mB] + chunk_sw(c, aF[mB])*16);
        LDM4(ah[mB], sb + A_HI + off);
        LDM4(al[mB], sb + A_LO + off);
      }
      uint32_t bh[4][2], bl[4][2];
      #pragma unroll
      for (int nB2 = 0; nB2 < 2; nB2++){
        int kl = ks*16 + b_k;
        int cn = wn*4 + nB2*2 + b_cadd;
        uint32_t off = (uint32_t)(kl*256 + chunk_sw(cn, swf(kl))*16);
        uint32_t r[4];
        LDM4T(r, sb + B_HI + off);
        bh[nB2*2][0]=r[0]; bh[nB2*2][1]=r[1];
        bh[nB2*2+1][0]=r[2]; bh[nB2*2+1][1]=r[3];
        LDM4T(r, sb + B_LO + off);
        bl[nB2*2][0]=r[0]; bl[nB2*2][1]=r[1];
        bl[nB2*2+1][0]=r[2]; bl[nB2*2+1][1]=r[3];
      }
      #pragma unroll
      for (int mB = 0; mB < 4; mB++)
        #pragma unroll
        for (int nB = 0; nB < 4; nB++){
          MMA16816(acc[mB][nB], ah[mB], bh[nB]);
          MMA16816(acc[mB][nB], ah[mB], bl[nB]);
          MMA16816(acc[mB][nB], al[mB], bh[nB]);
        }
    }
    __syncthreads();
  }

  float psum[4][2], psq[4][2];
  #pragma unroll
  for (int i=0;i<4;i++){ psum[i][0]=psum[i][1]=0.f; psq[i][0]=psq[i][1]=0.f; }

  #pragma unroll
  for (int mB = 0; mB < 4; mB++){
    int m1 = wm*64 + mB*16 + g;
    float b1 = bias[m0 + m1], b2 = bias[m0 + m1 + 8];
    #pragma unroll
    for (int nB = 0; nB < 4; nB++){
      int n = wn*32 + nB*8 + l2*2;
      float v0 = acc[mB][nB][0] + b1;
      float v1 = acc[mB][nB][1] + b1;
      float v2 = acc[mB][nB][2] + b2;
      float v3 = acc[mB][nB][3] + b2;
      if (SMAJOR){
        size_t r0 = ((size_t)b*SPB + s0 + n)*(size_t)Mtot + m0;
        Y[r0 + m1]                = v0;
        Y[r0 + Mtot + m1]         = v1;
        Y[r0 + m1 + 8]            = v2;
        Y[r0 + Mtot + m1 + 8]     = v3;
      } else {
        size_t r0 = ((size_t)b*Mtot + m0 + m1)*(size_t)SPB + s0 + n;
        float2 p01; p01.x = v0; p01.y = v1;
        *(float2*)&Y[r0] = p01;
        float2 p23; p23.x = v2; p23.y = v3;
        *(float2*)&Y[r0 + 8*(size_t)SPB] = p23;
      }
      psum[mB][0] += v0 + v1;  psq[mB][0] += v0*v0 + v1*v1;
      psum[mB][1] += v2 + v3;  psq[mB][1] += v2*v2 + v3*v3;
    }
  }
  #pragma unroll
  for (int mB = 0; mB < 4; mB++)
    #pragma unroll
    for (int h = 0; h < 2; h++){
      float s = psum[mB][h], q = psq[mB][h];
      s += __shfl_down_sync(0xffffffffu, s, 1, 4);
      s += __shfl_down_sync(0xffffffffu, s, 2, 4);
      q += __shfl_down_sync(0xffffffffu, q, 1, 4);
      q += __shfl_down_sync(0xffffffffu, q, 2, 4);
      if (l2 == 0){
        int m = m0 + wm*64 + mB*16 + g + h*8;
        atomicAdd(&g_ssum[statOff + m], s);
        atomicAdd(&g_ssq [statOff + m], q);
      }
    }
}

// ---------------- BN(gcm)+relu, attention softmax over c, max-pool over k ---
// reads half2 pairs (samples 2p,2p+1)
__global__ __launch_bounds__(128) void attnpool_kernel(
    const uint32_t* __restrict__ ygcm2, const float* __restrict__ w_att,
    const float* __restrict__ b_att, float* __restrict__ pooledT)
{
  __shared__ float watt[32];
  __shared__ float redm[4], reds[4];
  const int c = threadIdx.x;
  const int bn = blockIdx.x;                 // b*4096 + n
  if (c < 32) watt[c] = w_att[c];
  const float sc = g_scl[128+c], sh = g_sft[128+c];
  __syncthreads();
  const uint32_t* base = ygcm2 + (size_t)bn*16*128 + c;
  float logit = 0.f, mx = 0.f;
  #pragma unroll
  for (int p = 0; p < 16; p++){
    uint32_t u = base[(size_t)p*128];
    float2 f = __half22float2(*(__half2*)&u);
    float va = fmaxf(fmaf(sc, f.x, sh), 0.f);
    float vb = fmaxf(fmaf(sc, f.y, sh), 0.f);
    logit = fmaf(va, watt[2*p], fmaf(vb, watt[2*p+1], logit));
    mx = fmaxf(mx, fmaxf(va, vb));
  }
  logit += b_att[0];
  const int lane = c & 31, w = c >> 5;
  float m = logit;
  #pragma unroll
  for (int o=16;o>0;o>>=1) m = fmaxf(m, __shfl_xor_sync(0xffffffffu, m, o));
  if (lane==0) redm[w] = m;
  __syncthreads();
  m = fmaxf(fmaxf(redm[0],redm[1]), fmaxf(redm[2],redm[3]));
  float e = expf(logit - m);
  float s = e;
  #pragma unroll
  for (int o=16;o>0;o>>=1) s += __shfl_xor_sync(0xffffffffu, s, o);
  if (lane==0) reds[w] = s;
  __syncthreads();
  float tot = reds[0]+reds[1]+reds[2]+reds[3];
  float pooled = fmaf(mx, e/tot, mx);
  const int b = bn >> 12, n = bn & 4095;
  pooledT[((size_t)b*SCq + c)*(size_t)Nq + n] = pooled;
}

// ---------------- final: relu(bn(up)) + relu(bn(res)) -----------------------
__global__ __launch_bounds__(256) void combine_kernel(float* __restrict__ out){
  size_t i4 = (size_t)blockIdx.x*256 + threadIdx.x;
  size_t i = i4*4;
  int o = (int)((i >> 12) & 511);
  float su = g_scl[256+o], tu = g_sft[256+o];
  float sr = g_scl[768+o], th = g_sft[768+o];
  float4 u = *(const float4*)&g_yup[i];
  float4 r = *(const float4*)&g_yres[i];
  float4 y;
  y.x = fmaxf(fmaf(su,u.x,tu),0.f) + fmaxf(fmaf(sr,r.x,th),0.f);
  y.y = fmaxf(fmaf(su,u.y,tu),0.f) + fmaxf(fmaf(sr,r.y,th),0.f);
  y.z = fmaxf(fmaf(su,u.z,tu),0.f) + fmaxf(fmaf(sr,r.z,th),0.f);
  y.w = fmaxf(fmaf(su,u.w,tu),0.f) + fmaxf(fmaf(sr,r.w,th),0.f);
  *(float4*)&out[i] = y;
}

// ---------------- launch ----------------------------------------------------
extern "C" void kernel_launch(void* const* d_in, const int* in_sizes, int n_in,
                              void* d_out, int out_size){
  (void)in_sizes; (void)n_in; (void)out_size;
  const float* expanded = (const float*)d_in[0];
  const float* feature  = (const float*)d_in[1];
  const int*   gidx     = (const int*)d_in[2];
  const float* w_sub = (const float*)d_in[3];
  const float* b_sub = (const float*)d_in[4];
  const float* gg_sub= (const float*)d_in[5];
  const float* be_sub= (const float*)d_in[6];
  const float* w_gcm = (const float*)d_in[7];
  const float* b_gcm = (const float*)d_in[8];
  const float* gg_gcm= (const float*)d_in[9];
  const float* be_gcm= (const float*)d_in[10];
  const float* w_att = (const float*)d_in[11];
  const float* b_att = (const float*)d_in[12];
  const float* w_up  = (const float*)d_in[13];
  const float* b_up  = (const float*)d_in[14];
  const float* gg_up = (const float*)d_in[15];
  const float* be_up = (const float*)d_in[16];
  const float* w_res = (const float*)d_in[17];
  const float* b_res = (const float*)d_in[18];
  const float* gg_res= (const float*)d_in[19];
  const float* be_res= (const float*)d_in[20];
  float* out = (float*)d_out;

  float *p_subraw, *p_pool, *p_yup, *p_yres;
  uint32_t* p_ygcm2;
  cudaGetSymbolAddress((void**)&p_subraw, g_sub_raw);
  cudaGetSymbolAddress((void**)&p_ygcm2,  g_ygcm2);
  cudaGetSymbolAddress((void**)&p_pool,   g_pooledT);
  cudaGetSymbolAddress((void**)&p_yup,    g_yup);
  cudaGetSymbolAddress((void**)&p_yres,   g_yres);
  __nv_bfloat16 *p_wsub_hi, *p_wsub_lo, *p_wup_hi, *p_wup_lo, *p_wres_hi, *p_wres_lo;
  cudaGetSymbolAddress((void**)&p_wsub_hi, g_wsub_hi);
  cudaGetSymbolAddress((void**)&p_wsub_lo, g_wsub_lo);
  cudaGetSymbolAddress((void**)&p_wup_hi,  g_wup_hi);
  cudaGetSymbolAddress((void**)&p_wup_lo,  g_wup_lo);
  cudaGetSymbolAddress((void**)&p_wres_hi, g_wres_hi);
  cudaGetSymbolAddress((void**)&p_wres_lo, g_wres_lo);

  cudaFuncSetAttribute(gcm_mma_kernel,
                       cudaFuncAttributeMaxDynamicSharedMemorySize, G_SMEM);
  cudaFuncSetAttribute(lin_mma_kernel<256,true>,
                       cudaFuncAttributeMaxDynamicSharedMemorySize, 196608);
  cudaFuncSetAttribute(lin_mma_kernel<256,false>,
                       cudaFuncAttributeMaxDynamicSharedMemorySize, 196608);
  cudaFuncSetAttribute(lin_mma_kernel<128,false>,
                       cudaFuncAttributeMaxDynamicSharedMemorySize, 131072);

  // 1: zero stats + split all weights
  prep_all_kernel<<<1024, 256>>>(w_sub, w_gcm, w_up, w_res);
  // 2: sub conv -> sub_raw (b,n,c) + stats[0..128)
  lin_mma_kernel<256,true><<<dim3(32,1,4), 256, 196608>>>(
      p_wsub_hi, p_wsub_lo, feature, b_sub, p_subraw, 0, Nq, 128);
  // 3
  finalize_kernel<<<1,128>>>(gg_sub, be_sub, 0, 128, 1.f/16384.f);
  // 4: gcm conv (single fp16, fused gather + BN(sub)); 592 CTAs = 2 full waves
  gcm_mma_kernel<<<G_CTAS, 256, G_SMEM>>>(
      expanded, p_subraw, gidx, b_gcm, p_ygcm2);
  // 5
  finalize_kernel<<<1,128>>>(gg_gcm, be_gcm, 128, 128, 1.f/524288.f);
  // 6: attention + max-pool -> pooledT (b,c,n)
  attnpool_kernel<<<Bq*Nq,128>>>(p_ygcm2, w_att, b_att, p_pool);
  // 7: up conv (K=128) -> yup (b,o,n) + stats[256..768)
  lin_mma_kernel<128,false><<<dim3(32,4,4), 256, 131072>>>(
      p_wup_hi, p_wup_lo, p_pool, b_up, p_yup, 256, Nq, 512);
  // 8: res conv (K=256) -> yres (b,o,n) + stats[768..1280)
  lin_mma_kernel<256,false><<<dim3(32,4,4), 256, 196608>>>(
      p_wres_hi, p_wres_lo, feature, b_res, p_yres, 768, Nq, 512);
  // 9
  finalize2_kernel<<<8,128>>>(gg_up, be_up, gg_res, be_res);
  // 10: out = relu(bn(up)) + relu(bn(res))
  combine_kernel<<<8192,256>>>(out);
}